// round 1
// baseline (speedup 1.0000x reference)
#include <cuda_runtime.h>
#include <cstdint>

// StyleConvBase3D: modulated/demodulated 3D conv, B=8, Cin=Cout=32, D=48, K=3, VALID -> 46^3
// Inputs (metadata order): x, s, style_weight, style_bias, weight, bias. Output float32.

#define BB    8
#define CIN   32
#define COUT  32
#define DI    48
#define DO    46
#define NTAP  27

// Normalized modulated weights, layout [b][cin][tap][cout] (cout contiguous).
__device__ float g_wn[BB * CIN * NTAP * COUT];

static __device__ __forceinline__ unsigned long long pack2(float lo, float hi) {
    unsigned long long r;
    asm("mov.b64 %0, {%1, %2};" : "=l"(r) : "f"(lo), "f"(hi));
    return r;
}
static __device__ __forceinline__ void unpack2(unsigned long long v, float& lo, float& hi) {
    asm("mov.b64 {%0, %1}, %2;" : "=f"(lo), "=f"(hi) : "l"(v));
}
// Packed fp32x2 FMA (Blackwell): 2 fp32 FMAs per instruction.
static __device__ __forceinline__ unsigned long long ffma2(unsigned long long a,
                                                           unsigned long long b,
                                                           unsigned long long c) {
    unsigned long long d;
    asm("fma.rn.f32x2 %0, %1, %2, %3;" : "=l"(d) : "l"(a), "l"(b), "l"(c));
    return d;
}

// ---------------------------------------------------------------------------
// Kernel 1: style modulation + demodulation. One block per batch sample.
// ---------------------------------------------------------------------------
__global__ void prep_kernel(const float* __restrict__ s,
                            const float* __restrict__ style_weight,
                            const float* __restrict__ style_bias,
                            const float* __restrict__ weight) {
    const int b = blockIdx.x;
    __shared__ float smod[CIN];
    const int tid = threadIdx.x;        // 128 threads
    if (tid < CIN) {
        smod[tid] = s[b * 2 + 0] * style_weight[tid * 2 + 0]
                  + s[b * 2 + 1] * style_weight[tid * 2 + 1]
                  + style_bias[tid];
    }
    __syncthreads();

    const int warp = tid >> 5;
    const int lane = tid & 31;          // lane == cin

    for (int cout = warp; cout < COUT; cout += 4) {
        const float sm = smod[lane];
        const float* wp = weight + (cout * CIN + lane) * NTAP;
        float wv[NTAP];
        float ss = 0.f;
#pragma unroll
        for (int t = 0; t < NTAP; ++t) {
            wv[t] = wp[t] * sm;
            ss += wv[t] * wv[t];
        }
#pragma unroll
        for (int o = 16; o; o >>= 1) ss += __shfl_xor_sync(0xFFFFFFFFu, ss, o);
        const float inv = 1.0f / sqrtf(ss + 1e-8f);
#pragma unroll
        for (int t = 0; t < NTAP; ++t)
            g_wn[((b * CIN + lane) * NTAP + t) * COUT + cout] = wv[t] * inv;
    }
}

// ---------------------------------------------------------------------------
// Kernel 2: direct conv, FFMA2-packed over adjacent output channels.
// Block: one (b, z0, y-group). 192 threads = 6 x-groups x 8 y x 4 cout-groups.
// Thread: 8 couts x 8 x-points, held as 4 cout-pairs x 8 x in f32x2 regs.
// ---------------------------------------------------------------------------
__global__ void __launch_bounds__(192)
conv_kernel(const float* __restrict__ x,
            const float* __restrict__ bias,
            float* __restrict__ out) {
    const int yg = blockIdx.x;          // 0..5
    const int z0 = blockIdx.y;          // 0..45
    const int b  = blockIdx.z;          // 0..7
    const int y0 = yg * 8;

    const int tid = threadIdx.x;
    const int tx  = tid % 6;            // x-group: x0 = 8*tx
    const int ty  = (tid / 6) % 8;      // y within tile
    const int tc  = tid / 48;           // cout-group: couts 8*tc .. 8*tc+7
    const int x0  = tx * 8;

    __shared__ __align__(16) float sx[3 * 10 * DI];      // [kz][y(10)][x(48)]
    __shared__ __align__(16) float sw[NTAP * COUT];      // [tap][cout]

    unsigned long long acc[4][8];
#pragma unroll
    for (int cp = 0; cp < 4; ++cp)
#pragma unroll
        for (int xp = 0; xp < 8; ++xp) acc[cp][xp] = 0ull;

    for (int cin = 0; cin < CIN; ++cin) {
        __syncthreads();   // previous iteration's compute done before overwrite

        // --- load input tile: z0..z0+2, y0..y0+9 (guarded), full x row ---
        const float* xin = x + (((size_t)(b * CIN + cin) * DI + z0) * DI + y0) * DI;
        for (int i = tid; i < 360; i += 192) {           // 360 float4 = 1440 floats
            const int dz = i / 120;
            const int r  = i % 120;                      // float4 idx in 10x48 chunk
            const int dy = r / 12;
            float4 v = make_float4(0.f, 0.f, 0.f, 0.f);
            if (y0 + dy < DI)
                v = *reinterpret_cast<const float4*>(xin + dz * DI * DI + r * 4);
            reinterpret_cast<float4*>(sx)[dz * 120 + r] = v;
        }
        // --- load weight slice for this cin: [tap][cout], 864 floats ---
        {
            const float4* wn = reinterpret_cast<const float4*>(
                g_wn + (size_t)(b * CIN + cin) * NTAP * COUT);
            for (int i = tid; i < 216; i += 192)
                reinterpret_cast<float4*>(sw)[i] = wn[i];
        }
        __syncthreads();

#pragma unroll
        for (int kz = 0; kz < 3; ++kz) {
#pragma unroll
            for (int ky = 0; ky < 3; ++ky) {
                const float* row = sx + kz * 480 + (ty + ky) * DI + x0;
                const float4 va = *reinterpret_cast<const float4*>(row);
                const float4 vb = *reinterpret_cast<const float4*>(row + 4);
                const float2 vc = *reinterpret_cast<const float2*>(row + 8);
                unsigned long long xb[10];
                xb[0] = pack2(va.x, va.x); xb[1] = pack2(va.y, va.y);
                xb[2] = pack2(va.z, va.z); xb[3] = pack2(va.w, va.w);
                xb[4] = pack2(vb.x, vb.x); xb[5] = pack2(vb.y, vb.y);
                xb[6] = pack2(vb.z, vb.z); xb[7] = pack2(vb.w, vb.w);
                xb[8] = pack2(vc.x, vc.x); xb[9] = pack2(vc.y, vc.y);
#pragma unroll
                for (int kx = 0; kx < 3; ++kx) {
                    const int tap = (kz * 3 + ky) * 3 + kx;
                    const unsigned long long* wrow =
                        reinterpret_cast<const unsigned long long*>(sw + tap * COUT + 8 * tc);
                    const unsigned long long w0 = wrow[0];
                    const unsigned long long w1 = wrow[1];
                    const unsigned long long w2 = wrow[2];
                    const unsigned long long w3 = wrow[3];
#pragma unroll
                    for (int xp = 0; xp < 8; ++xp) {
                        const unsigned long long xv = xb[xp + kx];
                        acc[0][xp] = ffma2(xv, w0, acc[0][xp]);
                        acc[1][xp] = ffma2(xv, w1, acc[1][xp]);
                        acc[2][xp] = ffma2(xv, w2, acc[2][xp]);
                        acc[3][xp] = ffma2(xv, w3, acc[3][xp]);
                    }
                }
            }
        }
    }

    // --- epilogue: unpack, add bias, masked scalar stores ---
    const int y = y0 + ty;
    if (y < DO) {
#pragma unroll
        for (int cp = 0; cp < 4; ++cp) {
            const int c_even = 8 * tc + 2 * cp;
            const float b0 = bias[c_even];
            const float b1 = bias[c_even + 1];
            float* o0 = out + (((size_t)(b * COUT + c_even) * DO + z0) * DO + y) * DO;
            float* o1 = o0 + (size_t)DO * DO * DO;
#pragma unroll
            for (int xp = 0; xp < 8; ++xp) {
                const int xo = x0 + xp;
                if (xo < DO) {
                    float lo, hi;
                    unpack2(acc[cp][xp], lo, hi);
                    o0[xo] = lo + b0;
                    o1[xo] = hi + b1;
                }
            }
        }
    }
}

extern "C" void kernel_launch(void* const* d_in, const int* in_sizes, int n_in,
                              void* d_out, int out_size) {
    const float* x  = (const float*)d_in[0];
    const float* s  = (const float*)d_in[1];
    const float* sw = (const float*)d_in[2];
    const float* sb = (const float*)d_in[3];
    const float* w  = (const float*)d_in[4];
    const float* bs = (const float*)d_in[5];
    float* out = (float*)d_out;

    prep_kernel<<<BB, 128>>>(s, sw, sb, w);
    conv_kernel<<<dim3(6, DO, BB), 192>>>(x, bs, out);
}

// round 2
// speedup vs baseline: 1.1345x; 1.1345x over previous
#include <cuda_runtime.h>
#include <cstdint>

// StyleConvBase3D: modulated/demodulated 3D conv, B=8, Cin=Cout=32, D=48, K=3, VALID -> 46^3
// Inputs (metadata order): x, s, style_weight, style_bias, weight, bias. Output float32.

#define BB    8
#define CIN   32
#define COUT  32
#define DI    48
#define DO    46
#define NTAP  27

// Normalized modulated weights, layout [b][cin][tap][cout] (cout contiguous).
__device__ float g_wn[BB * CIN * NTAP * COUT];

static __device__ __forceinline__ unsigned long long pack2(float lo, float hi) {
    unsigned long long r;
    asm("mov.b64 %0, {%1, %2};" : "=l"(r) : "f"(lo), "f"(hi));
    return r;
}
static __device__ __forceinline__ void unpack2(unsigned long long v, float& lo, float& hi) {
    asm("mov.b64 {%0, %1}, %2;" : "=f"(lo), "=f"(hi) : "l"(v));
}
// Packed fp32x2 FMA (Blackwell): 2 fp32 FMAs per instruction.
static __device__ __forceinline__ unsigned long long ffma2(unsigned long long a,
                                                           unsigned long long b,
                                                           unsigned long long c) {
    unsigned long long d;
    asm("fma.rn.f32x2 %0, %1, %2, %3;" : "=l"(d) : "l"(a), "l"(b), "l"(c));
    return d;
}

// 16B async copy global->shared; srcbytes=0 zero-fills (for masked rows).
static __device__ __forceinline__ void cp_async16(uint32_t dst_smem, const void* src, int srcbytes) {
    asm volatile("cp.async.cg.shared.global [%0], [%1], 16, %2;"
                 :: "r"(dst_smem), "l"(src), "r"(srcbytes));
}
#define CP_COMMIT() asm volatile("cp.async.commit_group;")
#define CP_WAIT0()  asm volatile("cp.async.wait_group 0;")

// ---------------------------------------------------------------------------
// Kernel 1: style modulation + demodulation. One block per batch sample.
// ---------------------------------------------------------------------------
__global__ void prep_kernel(const float* __restrict__ s,
                            const float* __restrict__ style_weight,
                            const float* __restrict__ style_bias,
                            const float* __restrict__ weight) {
    const int b = blockIdx.x;
    __shared__ float smod[CIN];
    const int tid = threadIdx.x;        // 128 threads
    if (tid < CIN) {
        smod[tid] = s[b * 2 + 0] * style_weight[tid * 2 + 0]
                  + s[b * 2 + 1] * style_weight[tid * 2 + 1]
                  + style_bias[tid];
    }
    __syncthreads();

    const int warp = tid >> 5;
    const int lane = tid & 31;          // lane == cin

    for (int cout = warp; cout < COUT; cout += 4) {
        const float sm = smod[lane];
        const float* wp = weight + (cout * CIN + lane) * NTAP;
        float wv[NTAP];
        float ss = 0.f;
#pragma unroll
        for (int t = 0; t < NTAP; ++t) {
            wv[t] = wp[t] * sm;
            ss += wv[t] * wv[t];
        }
#pragma unroll
        for (int o = 16; o; o >>= 1) ss += __shfl_xor_sync(0xFFFFFFFFu, ss, o);
        const float inv = 1.0f / sqrtf(ss + 1e-8f);
#pragma unroll
        for (int t = 0; t < NTAP; ++t)
            g_wn[((b * CIN + lane) * NTAP + t) * COUT + cout] = wv[t] * inv;
    }
}

// ---------------------------------------------------------------------------
// Kernel 2: direct conv, FFMA2-packed over adjacent output channels.
// cp.async double-buffered over cin; ONE barrier per cin iteration.
// Block: one (b, z0, y-group). 192 threads = 6 x-groups x 8 y x 4 cout-groups.
// Thread: 8 couts x 8 x-points, held as 4 cout-pairs x 8 x in f32x2 regs.
// ---------------------------------------------------------------------------
__global__ void __launch_bounds__(192, 3)
conv_kernel(const float* __restrict__ x,
            const float* __restrict__ bias,
            float* __restrict__ out) {
    const int yg = blockIdx.x;          // 0..5
    const int z0 = blockIdx.y;          // 0..45
    const int b  = blockIdx.z;          // 0..7
    const int y0 = yg * 8;

    const int tid = threadIdx.x;
    const int tx  = tid % 6;            // x-group: x0 = 8*tx
    const int ty  = (tid / 6) % 8;      // y within tile
    const int tc  = tid / 48;           // cout-group: couts 8*tc .. 8*tc+7
    const int x0  = tx * 8;

    __shared__ __align__(16) float sx[2][3 * 10 * DI];   // [buf][kz][y(10)][x(48)]
    __shared__ __align__(16) float sw[2][NTAP * COUT];   // [buf][tap][cout]

    // Per-thread precomputed copy-slot descriptors (3 slots: 576 float4 / 192 thr)
    // slot j handles flat index i = tid + 192*j over [x-tile(360) | weights(216)].
    uint32_t sx_base = (uint32_t)__cvta_generic_to_shared(&sx[0][0]);
    uint32_t sw_base = (uint32_t)__cvta_generic_to_shared(&sw[0][0]);

    unsigned long long acc[4][8];
#pragma unroll
    for (int cp = 0; cp < 4; ++cp)
#pragma unroll
        for (int xp = 0; xp < 8; ++xp) acc[cp][xp] = 0ull;

    const float* xin_base = x + (((size_t)b * CIN * DI + z0) * DI + y0) * DI;
    const float* wn_base  = g_wn + (size_t)b * CIN * NTAP * COUT;

    // Issue loads for one cin into buffer p.
    auto issue_loads = [&](int cin, int p) {
        const float* xin = xin_base + (size_t)cin * DI * DI * DI;
        const uint32_t sxp = sx_base + (uint32_t)(p * 1440 * 4);
#pragma unroll
        for (int j = 0; j < 2; ++j) {
            const int i = tid + 192 * j;
            if (i < 360) {
                const int dz = i / 120;
                const int r  = i % 120;
                const int dy = r / 12;
                const int ok = (y0 + dy < DI) ? 16 : 0;
                cp_async16(sxp + (uint32_t)((dz * 120 + r) * 16),
                           xin + dz * (DI * DI) + r * 4, ok);
            }
        }
        const float* wn = wn_base + (size_t)cin * NTAP * COUT;
        const uint32_t swp = sw_base + (uint32_t)(p * 864 * 4);
        {
            const int i = tid;          // 216 float4, first 216 threads (wait, 216 > 192)
            if (i < 192) {
                cp_async16(swp + (uint32_t)(i * 16), wn + i * 4, 16);
            }
            const int i2 = tid + 192;
            if (i2 < 216) {
                cp_async16(swp + (uint32_t)(i2 * 16), wn + i2 * 4, 16);
            }
        }
        CP_COMMIT();
    };

    issue_loads(0, 0);

    for (int cin = 0; cin < CIN; ++cin) {
        const int p = cin & 1;
        CP_WAIT0();                    // buffer p landed
        __syncthreads();               // everyone done with compute(cin-1) on buf !p, sees buf p
        if (cin + 1 < CIN) issue_loads(cin + 1, p ^ 1);

        const float* sxp = sx[p];
        const float* swp = sw[p];

#pragma unroll
        for (int kz = 0; kz < 3; ++kz) {
#pragma unroll
            for (int ky = 0; ky < 3; ++ky) {
                const float* row = sxp + kz * 480 + (ty + ky) * DI + x0;
                const float4 va = *reinterpret_cast<const float4*>(row);
                const float4 vb = *reinterpret_cast<const float4*>(row + 4);
                const float2 vc = *reinterpret_cast<const float2*>(row + 8);
                unsigned long long xb[10];
                xb[0] = pack2(va.x, va.x); xb[1] = pack2(va.y, va.y);
                xb[2] = pack2(va.z, va.z); xb[3] = pack2(va.w, va.w);
                xb[4] = pack2(vb.x, vb.x); xb[5] = pack2(vb.y, vb.y);
                xb[6] = pack2(vb.z, vb.z); xb[7] = pack2(vb.w, vb.w);
                xb[8] = pack2(vc.x, vc.x); xb[9] = pack2(vc.y, vc.y);
#pragma unroll
                for (int kx = 0; kx < 3; ++kx) {
                    const int tap = (kz * 3 + ky) * 3 + kx;
                    const unsigned long long* wrow =
                        reinterpret_cast<const unsigned long long*>(swp + tap * COUT + 8 * tc);
                    const unsigned long long w0 = wrow[0];
                    const unsigned long long w1 = wrow[1];
                    const unsigned long long w2 = wrow[2];
                    const unsigned long long w3 = wrow[3];
#pragma unroll
                    for (int xp = 0; xp < 8; ++xp) {
                        const unsigned long long xv = xb[xp + kx];
                        acc[0][xp] = ffma2(xv, w0, acc[0][xp]);
                        acc[1][xp] = ffma2(xv, w1, acc[1][xp]);
                        acc[2][xp] = ffma2(xv, w2, acc[2][xp]);
                        acc[3][xp] = ffma2(xv, w3, acc[3][xp]);
                    }
                }
            }
        }
    }

    // --- epilogue: unpack, add bias, masked scalar stores ---
    const int y = y0 + ty;
    if (y < DO) {
#pragma unroll
        for (int cp = 0; cp < 4; ++cp) {
            const int c_even = 8 * tc + 2 * cp;
            const float b0 = bias[c_even];
            const float b1 = bias[c_even + 1];
            float* o0 = out + (((size_t)(b * COUT + c_even) * DO + z0) * DO + y) * DO;
            float* o1 = o0 + (size_t)DO * DO * DO;
#pragma unroll
            for (int xp = 0; xp < 8; ++xp) {
                const int xo = x0 + xp;
                if (xo < DO) {
                    float lo, hi;
                    unpack2(acc[cp][xp], lo, hi);
                    o0[xo] = lo + b0;
                    o1[xo] = hi + b1;
                }
            }
        }
    }
}

extern "C" void kernel_launch(void* const* d_in, const int* in_sizes, int n_in,
                              void* d_out, int out_size) {
    const float* x  = (const float*)d_in[0];
    const float* s  = (const float*)d_in[1];
    const float* sw = (const float*)d_in[2];
    const float* sb = (const float*)d_in[3];
    const float* w  = (const float*)d_in[4];
    const float* bs = (const float*)d_in[5];
    float* out = (float*)d_out;

    prep_kernel<<<BB, 128>>>(s, sw, sb, w);
    conv_kernel<<<dim3(6, DO, BB), 192>>>(x, bs, out);
}